// round 1
// baseline (speedup 1.0000x reference)
#include <cuda_runtime.h>
#include <cuda_bf16.h>
#include <cstdint>

#define NUM_TOKENS 8192
#define DIM        1024
#define INTER      4096
#define NE         8
#define MAXROWS    (NUM_TOKENS*2 + NE*128)   // 17408 (each expert segment padded to 128)
#define MAXTILES   (MAXROWS/128)             // 136

// ---------------- scratch (device globals: no allocations allowed) ----------------
__device__ float g_H[(size_t)MAXROWS * INTER];   // reused: shared H1 (rows 0..8191), then routed gathered H
__device__ int   g_perm[MAXROWS];
__device__ float g_wperm[MAXROWS];
__device__ int   g_tok_e[NUM_TOKENS*2];
__device__ float g_tok_w[NUM_TOKENS*2];
__device__ int   g_cnt[NE];
__device__ int   g_cursor[NE];
__device__ int   g_tile_e[MAXTILES];
__device__ int   g_tile_m[MAXTILES];
__device__ int   g_tile_end[MAXTILES];

// ---------------- small kernels ----------------
__global__ void init_kernel() {
    int i = blockIdx.x*256 + threadIdx.x;
    if (i < NE) g_cnt[i] = 0;
    if (i < MAXROWS) { g_perm[i] = 0; g_wperm[i] = 0.0f; }
}

__global__ void router_kernel(const float* __restrict__ x, const float* __restrict__ rw) {
    int w = (blockIdx.x*blockDim.x + threadIdx.x) >> 5;
    int lane = threadIdx.x & 31;
    if (w >= NUM_TOKENS) return;
    const float* xr = x + (size_t)w * DIM;
    float acc[NE];
#pragma unroll
    for (int e=0;e<NE;e++) acc[e]=0.f;
    for (int k = lane; k < DIM; k += 32) {
        float xv = xr[k];
        const float4 wa = *(const float4*)(rw + k*NE);
        const float4 wb = *(const float4*)(rw + k*NE + 4);
        acc[0] += xv*wa.x; acc[1] += xv*wa.y; acc[2] += xv*wa.z; acc[3] += xv*wa.w;
        acc[4] += xv*wb.x; acc[5] += xv*wb.y; acc[6] += xv*wb.z; acc[7] += xv*wb.w;
    }
#pragma unroll
    for (int off=16; off>0; off>>=1)
#pragma unroll
        for (int e=0;e<NE;e++) acc[e] += __shfl_xor_sync(0xffffffffu, acc[e], off);
    if (lane == 0) {
        float v0 = -1e30f, v1 = -1e30f; int i0=0, i1=0;
#pragma unroll
        for (int e=0;e<NE;e++) {
            float v = acc[e];
            if (v > v0) { v1=v0; i1=i0; v0=v; i0=e; }
            else if (v > v1) { v1=v; i1=e; }
        }
        float w0 = 1.0f/(1.0f + expf(v1 - v0));   // softmax over top-2, exact
        float w1 = 1.0f - w0;
        g_tok_e[2*w]=i0; g_tok_e[2*w+1]=i1;
        g_tok_w[2*w]=w0; g_tok_w[2*w+1]=w1;
        atomicAdd(&g_cnt[i0],1); atomicAdd(&g_cnt[i1],1);
    }
}

__global__ void scan_kernel() {
    if (threadIdx.x != 0 || blockIdx.x != 0) return;
    int off=0, tile=0;
    for (int e=0;e<NE;e++) {
        int c = g_cnt[e];
        g_cursor[e] = off;
        int end = off + c;
        int nt = (c + 127) >> 7;
        for (int i=0;i<nt;i++) {
            g_tile_e[tile]=e; g_tile_m[tile]=off + (i<<7); g_tile_end[tile]=end; tile++;
        }
        off += nt << 7;
    }
    for (; tile<MAXTILES; tile++) g_tile_e[tile] = -1;
}

__global__ void scatter_kernel() {
    int t = blockIdx.x*256 + threadIdx.x;
    if (t >= NUM_TOKENS) return;
#pragma unroll
    for (int k=0;k<2;k++) {
        int e = g_tok_e[2*t+k];
        int p = atomicAdd(&g_cursor[e], 1);
        g_perm[p] = t;
        g_wperm[p] = g_tok_w[2*t+k];
    }
}

// ---------------- tf32 GEMM ----------------
__device__ __forceinline__ float tf32r(float f) {
    uint32_t u; asm("cvt.rna.tf32.f32 %0, %1;" : "=r"(u) : "f"(f));
    return __uint_as_float(u);
}

// C[M,N] = [relu]( A[M,K] @ W[K,N] ), optional grouped experts / row gather / scatter-add epilogue
template<int KD, int ND, bool GROUPED, bool GATHER, bool A_H, bool C_H, bool RELU, bool SCATTER>
__global__ void gemm_tf32(const float* __restrict__ Ain, const float* __restrict__ Wb,
                          float* __restrict__ Cout) {
    constexpr int BM=128, BN=128, BK=32;
    constexpr int AS=36;   // A smem row stride (conflict-free loads & 16B-aligned stores)
    constexpr int BS=132;  // B smem row stride
    extern __shared__ float sm_[];
    float* sA = sm_;                 // [2][BM][AS]
    float* sB = sm_ + 2*BM*AS;       // [2][BK][BS]

    const float* A = A_H ? (const float*)g_H : Ain;
    float* C = C_H ? (float*)g_H : Cout;

    int mbase, segEnd = 0;
    const float* W;
    if (GROUPED) {
        int e = g_tile_e[blockIdx.y];
        if (e < 0) return;
        mbase = g_tile_m[blockIdx.y];
        segEnd = g_tile_end[blockIdx.y];
        W = Wb + (size_t)e * KD * ND;
    } else {
        mbase = blockIdx.y * BM;
        W = Wb;
    }
    const int nbase = blockIdx.x * BN;

    const int tid  = threadIdx.x;
    const int lane = tid & 31, warp = tid >> 5;
    const int wr = warp & 3, wc = warp >> 2;           // 4x2 warp grid -> warp tile 32x64
    const int gid = lane >> 2, tid4 = lane & 3;

    // A tile global mapping: idx = tid + i*256 -> row = idx>>3 , k4 = idx&7 (coalesced 128B/8 lanes)
    const float* aPtr[4];
    int ar[4], ak4[4];
#pragma unroll
    for (int i=0;i<4;i++) {
        int idx = tid + i*256;
        ar[i] = idx >> 3; ak4[i] = idx & 7;
        int grow = mbase + ar[i];
        if (GATHER) grow = g_perm[grow];
        aPtr[i] = A + (size_t)grow * KD + ak4[i]*4;
    }
    // B tile global mapping: per i, k-row = warp + 8i (const per warp), n4 = lane (512B coalesced)
    const float* bPtr[4];
#pragma unroll
    for (int i=0;i<4;i++)
        bPtr[i] = W + (size_t)(warp + 8*i) * ND + nbase + lane*4;

    float acc[2][8][4];
#pragma unroll
    for (int a=0;a<2;a++)
#pragma unroll
        for (int b=0;b<8;b++)
#pragma unroll
            for (int c=0;c<4;c++) acc[a][b][c]=0.f;

    float4 ra[4], rb[4];
#pragma unroll
    for (int i=0;i<4;i++) ra[i] = *(const float4*)aPtr[i];
#pragma unroll
    for (int i=0;i<4;i++) rb[i] = *(const float4*)bPtr[i];

    // prologue store -> buffer 0
#pragma unroll
    for (int i=0;i<4;i++) {
        float* p = sA + ar[i]*AS + ak4[i]*4;
        p[0]=tf32r(ra[i].x); p[1]=tf32r(ra[i].y); p[2]=tf32r(ra[i].z); p[3]=tf32r(ra[i].w);
    }
#pragma unroll
    for (int i=0;i<4;i++) {
        float4 v; v.x=tf32r(rb[i].x); v.y=tf32r(rb[i].y); v.z=tf32r(rb[i].z); v.w=tf32r(rb[i].w);
        *(float4*)(sB + (warp+8*i)*BS + lane*4) = v;
    }
    __syncthreads();

    const int KT = KD / BK;
    for (int kt=0; kt<KT; kt++) {
        if (kt+1 < KT) {
#pragma unroll
            for (int i=0;i<4;i++) ra[i] = *(const float4*)(aPtr[i] + (kt+1)*BK);
#pragma unroll
            for (int i=0;i<4;i++) rb[i] = *(const float4*)(bPtr[i] + (size_t)(kt+1)*BK*ND);
        }
        const float* cA = sA + (kt&1)*BM*AS;
        const float* cB = sB + (kt&1)*BK*BS;
#pragma unroll
        for (int kg=0;kg<4;kg++) {
            uint32_t af[2][4];
#pragma unroll
            for (int mi=0;mi<2;mi++) {
                const float* p = cA + (wr*32 + mi*16 + gid)*AS + kg*8 + tid4;
                af[mi][0] = __float_as_uint(p[0]);
                af[mi][1] = __float_as_uint(p[8*AS]);
                af[mi][2] = __float_as_uint(p[4]);
                af[mi][3] = __float_as_uint(p[8*AS + 4]);
            }
#pragma unroll
            for (int ni=0;ni<8;ni++) {
                int n = wc*64 + ni*8 + gid;
                uint32_t b0 = __float_as_uint(cB[(kg*8 + tid4)*BS + n]);
                uint32_t b1 = __float_as_uint(cB[(kg*8 + tid4 + 4)*BS + n]);
#pragma unroll
                for (int mi=0;mi<2;mi++) {
                    asm volatile(
                        "mma.sync.aligned.m16n8k8.row.col.f32.tf32.tf32.f32 "
                        "{%0,%1,%2,%3}, {%4,%5,%6,%7}, {%8,%9}, {%0,%1,%2,%3};\n"
                        : "+f"(acc[mi][ni][0]), "+f"(acc[mi][ni][1]),
                          "+f"(acc[mi][ni][2]), "+f"(acc[mi][ni][3])
                        : "r"(af[mi][0]), "r"(af[mi][1]), "r"(af[mi][2]), "r"(af[mi][3]),
                          "r"(b0), "r"(b1));
                }
            }
        }
        if (kt+1 < KT) {
            float* dA = sA + ((kt+1)&1)*BM*AS;
            float* dB = sB + ((kt+1)&1)*BK*BS;
#pragma unroll
            for (int i=0;i<4;i++) {
                float* p = dA + ar[i]*AS + ak4[i]*4;
                p[0]=tf32r(ra[i].x); p[1]=tf32r(ra[i].y); p[2]=tf32r(ra[i].z); p[3]=tf32r(ra[i].w);
            }
#pragma unroll
            for (int i=0;i<4;i++) {
                float4 v; v.x=tf32r(rb[i].x); v.y=tf32r(rb[i].y); v.z=tf32r(rb[i].z); v.w=tf32r(rb[i].w);
                *(float4*)(dB + (warp+8*i)*BS + lane*4) = v;
            }
            __syncthreads();
        }
    }

    // epilogue
#pragma unroll
    for (int mi=0;mi<2;mi++) {
        int r0 = mbase + wr*32 + mi*16 + gid;
        int r1 = r0 + 8;
        if (SCATTER) {
            bool v0 = r0 < segEnd, v1 = r1 < segEnd;
            int t0=0, t1=0; float w0=0.f, w1=0.f;
            if (v0) { t0 = g_perm[r0]; w0 = g_wperm[r0]; }
            if (v1) { t1 = g_perm[r1]; w1 = g_wperm[r1]; }
#pragma unroll
            for (int ni=0;ni<8;ni++) {
                int c = nbase + wc*64 + ni*8 + tid4*2;
                if (v0) {
                    atomicAdd(&C[(size_t)t0*ND + c],     w0*acc[mi][ni][0]);
                    atomicAdd(&C[(size_t)t0*ND + c + 1], w0*acc[mi][ni][1]);
                }
                if (v1) {
                    atomicAdd(&C[(size_t)t1*ND + c],     w1*acc[mi][ni][2]);
                    atomicAdd(&C[(size_t)t1*ND + c + 1], w1*acc[mi][ni][3]);
                }
            }
        } else {
#pragma unroll
            for (int ni=0;ni<8;ni++) {
                int c = nbase + wc*64 + ni*8 + tid4*2;
                float x0=acc[mi][ni][0], x1=acc[mi][ni][1], x2=acc[mi][ni][2], x3=acc[mi][ni][3];
                if (RELU) { x0=fmaxf(x0,0.f); x1=fmaxf(x1,0.f); x2=fmaxf(x2,0.f); x3=fmaxf(x3,0.f); }
                C[(size_t)r0*ND + c]     = x0;
                C[(size_t)r0*ND + c + 1] = x1;
                C[(size_t)r1*ND + c]     = x2;
                C[(size_t)r1*ND + c + 1] = x3;
            }
        }
    }
}

// ---------------- launch ----------------
extern "C" void kernel_launch(void* const* d_in, const int* in_sizes, int n_in,
                              void* d_out, int out_size) {
    const float* x   = (const float*)d_in[0];
    const float* sw1 = (const float*)d_in[1];
    const float* sw2 = (const float*)d_in[2];
    const float* rw1 = (const float*)d_in[3];
    const float* rw2 = (const float*)d_in[4];
    const float* rtw = (const float*)d_in[5];
    float* out = (float*)d_out;

    constexpr int SMEM = (2*128*36 + 2*32*132) * 4;   // 70656 bytes

    auto s1 = gemm_tf32<DIM,   INTER, false, false, false, true,  true,  false>;
    auto s2 = gemm_tf32<INTER, DIM,   false, false, true,  false, false, false>;
    auto r1 = gemm_tf32<DIM,   INTER, true,  true,  false, true,  true,  false>;
    auto r2 = gemm_tf32<INTER, DIM,   true,  false, true,  false, false, true >;

    cudaFuncSetAttribute(s1, cudaFuncAttributeMaxDynamicSharedMemorySize, SMEM);
    cudaFuncSetAttribute(s2, cudaFuncAttributeMaxDynamicSharedMemorySize, SMEM);
    cudaFuncSetAttribute(r1, cudaFuncAttributeMaxDynamicSharedMemorySize, SMEM);
    cudaFuncSetAttribute(r2, cudaFuncAttributeMaxDynamicSharedMemorySize, SMEM);

    init_kernel   <<<(MAXROWS + 255)/256, 256>>>();
    router_kernel <<<NUM_TOKENS/8, 256>>>(x, rtw);
    scan_kernel   <<<1, 32>>>();
    scatter_kernel<<<(NUM_TOKENS + 255)/256, 256>>>();

    // shared expert FFN
    s1<<<dim3(INTER/128, NUM_TOKENS/128), 256, SMEM>>>(x, sw1, nullptr);
    s2<<<dim3(DIM/128,   NUM_TOKENS/128), 256, SMEM>>>(nullptr, sw2, out);
    // routed experts (grouped, gathered), atomically added on top of shared output
    r1<<<dim3(INTER/128, MAXTILES), 256, SMEM>>>(x, rw1, nullptr);
    r2<<<dim3(DIM/128,   MAXTILES), 256, SMEM>>>(nullptr, rw2, out);
}

// round 3
// speedup vs baseline: 2.0391x; 2.0391x over previous
#include <cuda_runtime.h>
#include <cuda_fp16.h>
#include <cstdint>

#define NT    8192
#define DIM   1024
#define INTER 4096
#define NE    8
#define MAXROWS  17408      // 2*NT + NE*128 (expert segments padded to 128)
#define MAXTILES 136        // MAXROWS/128

// ---------------- scratch (device globals: no allocations allowed) ----------------
__device__ __half g_xh[(size_t)NT * DIM];
__device__ __half g_H[(size_t)MAXROWS * INTER];
__device__ __half g_w1t[(size_t)(NE + 1) * INTER * DIM];   // [1+E][INTER][DIM]  (W1^T, K-major)
__device__ __half g_w2t[(size_t)(NE + 1) * DIM * INTER];   // [1+E][DIM][INTER]  (W2^T, K-major)
__device__ float  g_P[(size_t)MAXROWS * DIM];              // routed partials (permuted rows)
__device__ int    g_perm[MAXROWS];
__device__ float  g_wperm[MAXROWS];
__device__ int    g_pos[NT * 2];
__device__ int    g_tok_e[NT * 2];
__device__ float  g_tok_w[NT * 2];
__device__ int    g_cnt[NE];
__device__ int    g_cursor[NE];
__device__ int    g_tile_e[MAXTILES];
__device__ int    g_tile_m[MAXTILES];

// ---------------- PTX helpers ----------------
__device__ __forceinline__ uint32_t smem_u32(const void* p) {
    uint32_t a;
    asm("{ .reg .u64 t; cvta.to.shared.u64 t, %1; cvt.u32.u64 %0, t; }" : "=r"(a) : "l"(p));
    return a;
}
__device__ __forceinline__ void ldm4(uint32_t* r, uint32_t addr) {
    asm volatile("ldmatrix.sync.aligned.m8n8.x4.shared.b16 {%0,%1,%2,%3}, [%4];"
                 : "=r"(r[0]), "=r"(r[1]), "=r"(r[2]), "=r"(r[3]) : "r"(addr));
}
__device__ __forceinline__ void mma16816(float* d, const uint32_t* a, uint32_t b0, uint32_t b1) {
    asm volatile(
        "mma.sync.aligned.m16n8k16.row.col.f32.f16.f16.f32 "
        "{%0,%1,%2,%3},{%4,%5,%6,%7},{%8,%9},{%0,%1,%2,%3};"
        : "+f"(d[0]), "+f"(d[1]), "+f"(d[2]), "+f"(d[3])
        : "r"(a[0]), "r"(a[1]), "r"(a[2]), "r"(a[3]), "r"(b0), "r"(b1));
}

// ---------------- small kernels ----------------
__global__ void init_kernel() {
    int i = blockIdx.x * 256 + threadIdx.x;
    if (i < NE) g_cnt[i] = 0;
    if (i < MAXROWS) { g_perm[i] = 0; g_wperm[i] = 0.0f; }
}

__global__ void router_kernel(const float* __restrict__ x, const float* __restrict__ rw) {
    int w = (blockIdx.x * blockDim.x + threadIdx.x) >> 5;
    int lane = threadIdx.x & 31;
    if (w >= NT) return;
    const float* xr = x + (size_t)w * DIM;
    float acc[NE];
#pragma unroll
    for (int e = 0; e < NE; e++) acc[e] = 0.f;
    for (int k = lane; k < DIM; k += 32) {
        float xv = xr[k];
        const float4 wa = *(const float4*)(rw + k * NE);
        const float4 wb = *(const float4*)(rw + k * NE + 4);
        acc[0] += xv*wa.x; acc[1] += xv*wa.y; acc[2] += xv*wa.z; acc[3] += xv*wa.w;
        acc[4] += xv*wb.x; acc[5] += xv*wb.y; acc[6] += xv*wb.z; acc[7] += xv*wb.w;
    }
#pragma unroll
    for (int off = 16; off > 0; off >>= 1)
#pragma unroll
        for (int e = 0; e < NE; e++) acc[e] += __shfl_xor_sync(0xffffffffu, acc[e], off);
    if (lane == 0) {
        float v0 = -1e30f, v1 = -1e30f; int i0 = 0, i1 = 0;
#pragma unroll
        for (int e = 0; e < NE; e++) {
            float v = acc[e];
            if (v > v0) { v1 = v0; i1 = i0; v0 = v; i0 = e; }
            else if (v > v1) { v1 = v; i1 = e; }
        }
        float w0 = 1.0f / (1.0f + expf(v1 - v0));
        float w1 = 1.0f - w0;
        g_tok_e[2*w] = i0; g_tok_e[2*w+1] = i1;
        g_tok_w[2*w] = w0; g_tok_w[2*w+1] = w1;
        atomicAdd(&g_cnt[i0], 1); atomicAdd(&g_cnt[i1], 1);
    }
}

__global__ void scan_kernel() {
    if (threadIdx.x != 0 || blockIdx.x != 0) return;
    int off = 0, tile = 0;
    for (int e = 0; e < NE; e++) {
        int c = g_cnt[e];
        g_cursor[e] = off;
        int nt = (c + 127) >> 7;
        for (int i = 0; i < nt; i++) {
            g_tile_e[tile] = e; g_tile_m[tile] = off + (i << 7); tile++;
        }
        off += nt << 7;
    }
    for (; tile < MAXTILES; tile++) g_tile_e[tile] = -1;
}

__global__ void scatter_kernel() {
    int t = blockIdx.x * 256 + threadIdx.x;
    if (t >= NT) return;
#pragma unroll
    for (int k = 0; k < 2; k++) {
        int e = g_tok_e[2*t + k];
        int p = atomicAdd(&g_cursor[e], 1);
        g_perm[p] = t;
        g_wperm[p] = g_tok_w[2*t + k];
        g_pos[2*t + k] = p;
    }
}

__global__ void cvtx_kernel(const float* __restrict__ x) {
    size_t i = ((size_t)blockIdx.x * 256 + threadIdx.x) * 4;
    float4 v = *(const float4*)(x + i);
    union { __half2 h[2]; uint2 u; } pk;
    pk.h[0] = __floats2half2_rn(v.x, v.y);
    pk.h[1] = __floats2half2_rn(v.z, v.w);
    *(uint2*)(g_xh + i) = pk.u;
}

// transpose + convert: in fp32 [R,C] (row-major) -> out fp16 [C,R] (K-major for MMA)
__global__ void tcvt_kernel(const float* __restrict__ in, int w2sel, size_t outOff, int R, int C) {
    __shared__ float t[32][33];
    int z = blockIdx.z;
    in += (size_t)z * R * C;
    __half* out = (w2sel ? g_w2t : g_w1t) + outOff + (size_t)z * R * C;
    int r0 = blockIdx.y * 32, c0 = blockIdx.x * 32;
    int tx = threadIdx.x, ty = threadIdx.y;
#pragma unroll
    for (int i = 0; i < 32; i += 8)
        t[ty + i][tx] = in[(size_t)(r0 + ty + i) * C + (c0 + tx)];
    __syncthreads();
#pragma unroll
    for (int i = 0; i < 32; i += 8)
        out[(size_t)(c0 + ty + i) * R + (r0 + tx)] = __float2half(t[tx][ty + i]);
}

__global__ void combine_kernel(float* __restrict__ out) {
    int t = blockIdx.x;
    int c = threadIdx.x * 4;
    int p0 = g_pos[2*t], p1 = g_pos[2*t + 1];
    float w0 = g_wperm[p0], w1 = g_wperm[p1];
    float4 o = *(float4*)(out + (size_t)t * DIM + c);
    float4 a = *(const float4*)(g_P + (size_t)p0 * DIM + c);
    float4 b = *(const float4*)(g_P + (size_t)p1 * DIM + c);
    o.x += w0*a.x + w1*b.x; o.y += w0*a.y + w1*b.y;
    o.z += w0*a.z + w1*b.z; o.w += w0*a.w + w1*b.w;
    *(float4*)(out + (size_t)t * DIM + c) = o;
}

// ---------------- fp16 HMMA GEMM: C[128,128-tile] = A[128,K] @ B^T, B stored [N,K] ----------------
// CDST: 0 -> g_H (fp16, relu), 1 -> outp (fp32), 2 -> g_P (fp32)
template<int KD, int ND, bool GROUPED, bool GATHER, bool RELU, int CDST, bool A_H, bool W1SEL>
__global__ void __launch_bounds__(256, 2) gemm_hmma(float* __restrict__ outp) {
    constexpr int BK = 32, KT = KD / BK;
    constexpr int AST = 40;                       // halves per smem row (80B: conflict-free ldmatrix)
    constexpr int TILEH = 128 * AST;              // 5120 halves per tile
    constexpr int BUFH = 2 * TILEH;               // A+B per buffer
    __shared__ __half sm[2 * BUFH];               // 40960 bytes

    const __half* A = A_H ? g_H : g_xh;
    const __half* B = W1SEL ? g_w1t : g_w2t;
    int mbase;
    if (GROUPED) {
        int e = g_tile_e[blockIdx.y];
        if (e < 0) return;
        mbase = g_tile_m[blockIdx.y];
        B += (size_t)(1 + e) * KD * ND;
    } else {
        mbase = blockIdx.y * 128;
    }
    const int nbase = blockIdx.x * 128;
    const int tid = threadIdx.x, warp = tid >> 5, lane = tid & 31;
    const int wr = warp & 3, wc = warp >> 2;      // warp tile 32(m) x 64(n)
    const int g = lane >> 2, tg = lane & 3;

    // global load mapping: idx -> row idx>>2, 8-half chunk idx&3
    const __half* aPtr[2]; const __half* bPtr[2];
    int soff[2];
#pragma unroll
    for (int i = 0; i < 2; i++) {
        int idx = tid + i * 256, row = idx >> 2, ch = idx & 3;
        soff[i] = row * AST + ch * 8;
        int ar = mbase + row;
        if (GATHER) ar = g_perm[ar];
        aPtr[i] = A + (size_t)ar * KD + ch * 8;
        bPtr[i] = B + (size_t)(nbase + row) * KD + ch * 8;
    }

    // ldmatrix address bases (bytes): row = (lane&7) + bit3*8, kcol = bit4*8
    const int lr = (lane & 7) + ((lane >> 3) & 1) * 8;
    const int lk = (lane >> 4) * 8;
    const uint32_t smb = smem_u32(sm);
    const uint32_t aBase = smb + ((wr * 32 + lr) * AST + lk) * 2;
    const uint32_t bBase = smb + TILEH * 2 + ((wc * 64 + lr) * AST + lk) * 2;

    float acc[2][8][4];
#pragma unroll
    for (int a = 0; a < 2; a++)
#pragma unroll
        for (int b = 0; b < 8; b++)
#pragma unroll
            for (int c = 0; c < 4; c++) acc[a][b][c] = 0.f;

    uint4 ra[2], rb[2];
#pragma unroll
    for (int i = 0; i < 2; i++) ra[i] = *(const uint4*)aPtr[i];
#pragma unroll
    for (int i = 0; i < 2; i++) rb[i] = *(const uint4*)bPtr[i];
#pragma unroll
    for (int i = 0; i < 2; i++) *(uint4*)(sm + soff[i]) = ra[i];
#pragma unroll
    for (int i = 0; i < 2; i++) *(uint4*)(sm + TILEH + soff[i]) = rb[i];
    __syncthreads();

    for (int kt = 0; kt < KT; kt++) {
        if (kt + 1 < KT) {
#pragma unroll
            for (int i = 0; i < 2; i++) ra[i] = *(const uint4*)(aPtr[i] + (kt + 1) * BK);
#pragma unroll
            for (int i = 0; i < 2; i++) rb[i] = *(const uint4*)(bPtr[i] + (kt + 1) * BK);
        }
        const uint32_t ab = aBase + (kt & 1) * (BUFH * 2);
        const uint32_t bb = bBase + (kt & 1) * (BUFH * 2);
#pragma unroll
        for (int kg = 0; kg < 2; kg++) {
            uint32_t af[2][4];
            ldm4(af[0], ab + kg * 32);
            ldm4(af[1], ab + 1280 + kg * 32);    // +16 rows
#pragma unroll
            for (int nj = 0; nj < 4; nj++) {
                uint32_t bf[4];
                ldm4(bf, bb + nj * 1280 + kg * 32);
                mma16816(acc[0][2*nj],     af[0], bf[0], bf[2]);
                mma16816(acc[0][2*nj + 1], af[0], bf[1], bf[3]);
                mma16816(acc[1][2*nj],     af[1], bf[0], bf[2]);
                mma16816(acc[1][2*nj + 1], af[1], bf[1], bf[3]);
            }
        }
        if (kt + 1 < KT) {
            __half* d = sm + ((kt + 1) & 1) * BUFH;
#pragma unroll
            for (int i = 0; i < 2; i++) *(uint4*)(d + soff[i]) = ra[i];
#pragma unroll
            for (int i = 0; i < 2; i++) *(uint4*)(d + TILEH + soff[i]) = rb[i];
            __syncthreads();
        }
    }

    // epilogue: d0,d1 -> (row g, cols 2tg..), d2,d3 -> (row g+8, same cols)
#pragma unroll
    for (int mi = 0; mi < 2; mi++) {
        const int r0 = mbase + wr * 32 + mi * 16 + g;
#pragma unroll
        for (int ni = 0; ni < 8; ni++) {
            const int c = nbase + wc * 64 + ni * 8 + tg * 2;
            float x0 = acc[mi][ni][0], x1 = acc[mi][ni][1];
            float x2 = acc[mi][ni][2], x3 = acc[mi][ni][3];
            if (RELU) { x0 = fmaxf(x0, 0.f); x1 = fmaxf(x1, 0.f);
                        x2 = fmaxf(x2, 0.f); x3 = fmaxf(x3, 0.f); }
            if (CDST == 0) {
                *(__half2*)(g_H + (size_t)r0 * ND + c)       = __floats2half2_rn(x0, x1);
                *(__half2*)(g_H + (size_t)(r0 + 8) * ND + c) = __floats2half2_rn(x2, x3);
            } else {
                float* base = (CDST == 1) ? outp : (float*)g_P;
                *(float2*)(base + (size_t)r0 * ND + c)       = make_float2(x0, x1);
                *(float2*)(base + (size_t)(r0 + 8) * ND + c) = make_float2(x2, x3);
            }
        }
    }
}

// ---------------- launch ----------------
extern "C" void kernel_launch(void* const* d_in, const int* in_sizes, int n_in,
                              void* d_out, int out_size) {
    const float* x   = (const float*)d_in[0];
    const float* sw1 = (const float*)d_in[1];
    const float* sw2 = (const float*)d_in[2];
    const float* rw1 = (const float*)d_in[3];
    const float* rw2 = (const float*)d_in[4];
    const float* rtw = (const float*)d_in[5];
    float* out = (float*)d_out;

    init_kernel   <<<(MAXROWS + 255) / 256, 256>>>();
    router_kernel <<<NT / 8, 256>>>(x, rtw);
    scan_kernel   <<<1, 32>>>();
    scatter_kernel<<<NT / 256, 256>>>();

    cvtx_kernel<<<NT * DIM / 1024, 256>>>(x);
    dim3 tb(32, 8);
    tcvt_kernel<<<dim3(INTER/32, DIM/32, 1),  tb>>>(sw1, 0, 0, DIM, INTER);
    tcvt_kernel<<<dim3(DIM/32, INTER/32, 1),  tb>>>(sw2, 1, 0, INTER, DIM);
    tcvt_kernel<<<dim3(INTER/32, DIM/32, NE), tb>>>(rw1, 0, (size_t)INTER * DIM, DIM, INTER);
    tcvt_kernel<<<dim3(DIM/32, INTER/32, NE), tb>>>(rw2, 1, (size_t)DIM * INTER, INTER, DIM);

    // shared expert FFN
    gemm_hmma<DIM,   INTER, false, false, true,  0, false, true ><<<dim3(INTER/128, NT/128), 256>>>(out);
    gemm_hmma<INTER, DIM,   false, false, false, 1, true,  false><<<dim3(DIM/128,   NT/128), 256>>>(out);
    // routed experts (grouped, gathered), partials combined afterwards
    gemm_hmma<DIM,   INTER, true,  true,  true,  0, false, true ><<<dim3(INTER/128, MAXTILES), 256>>>(out);
    gemm_hmma<INTER, DIM,   true,  false, false, 2, true,  false><<<dim3(DIM/128,   MAXTILES), 256>>>(out);

    combine_kernel<<<NT, 256>>>(out);
}

// round 6
// speedup vs baseline: 2.2496x; 1.1032x over previous
#include <cuda_runtime.h>
#include <cuda_fp16.h>
#include <cstdint>

#define NT    8192
#define DIM   1024
#define INTER 4096
#define NE    8
#define MAXROWS  17408      // 2*NT + NE*128 (expert segments padded to 128)
#define MAXTILES 136        // MAXROWS/128

// ---------------- scratch (device globals: no allocations allowed) ----------------
__device__ __half g_xh[(size_t)NT * DIM];
__device__ __half g_H[(size_t)MAXROWS * INTER];
__device__ __half g_w1t[(size_t)(NE + 1) * INTER * DIM];   // [1+E][INTER][DIM]  (W1^T, K-major)
__device__ __half g_w2t[(size_t)(NE + 1) * DIM * INTER];   // [1+E][DIM][INTER]  (W2^T, K-major)
__device__ float  g_P[(size_t)MAXROWS * DIM];              // routed partials (permuted rows)
__device__ int    g_perm[MAXROWS];
__device__ float  g_wperm[MAXROWS];
__device__ int    g_pos[NT * 2];
__device__ int    g_tok_e[NT * 2];
__device__ float  g_tok_w[NT * 2];
__device__ int    g_cnt[NE];
__device__ int    g_cursor[NE];
__device__ int    g_tile_e[MAXTILES];
__device__ int    g_tile_m[MAXTILES];

// ---------------- PTX helpers ----------------
__device__ __forceinline__ uint32_t smem_u32(const void* p) {
    uint32_t a;
    asm("{ .reg .u64 t; cvta.to.shared.u64 t, %1; cvt.u32.u64 %0, t; }" : "=r"(a) : "l"(p));
    return a;
}
__device__ __forceinline__ void ldm4(uint32_t* r, uint32_t addr) {
    asm volatile("ldmatrix.sync.aligned.m8n8.x4.shared.b16 {%0,%1,%2,%3}, [%4];"
                 : "=r"(r[0]), "=r"(r[1]), "=r"(r[2]), "=r"(r[3]) : "r"(addr));
}
__device__ __forceinline__ void mma16816(float* d, const uint32_t* a, uint32_t b0, uint32_t b1) {
    asm volatile(
        "mma.sync.aligned.m16n8k16.row.col.f32.f16.f16.f32 "
        "{%0,%1,%2,%3},{%4,%5,%6,%7},{%8,%9},{%0,%1,%2,%3};"
        : "+f"(d[0]), "+f"(d[1]), "+f"(d[2]), "+f"(d[3])
        : "r"(a[0]), "r"(a[1]), "r"(a[2]), "r"(a[3]), "r"(b0), "r"(b1));
}
__device__ __forceinline__ void cpa16(uint32_t dst, const void* src) {
    asm volatile("cp.async.cg.shared.global [%0], [%1], 16;" :: "r"(dst), "l"(src));
}

// ---------------- small kernels ----------------
__global__ void init_kernel() {
    int i = blockIdx.x * 256 + threadIdx.x;
    if (i < NE) g_cnt[i] = 0;
    if (i < MAXROWS) { g_perm[i] = 0; g_wperm[i] = 0.0f; }
}

__global__ void router_kernel(const float* __restrict__ x, const float* __restrict__ rw) {
    int w = (blockIdx.x * blockDim.x + threadIdx.x) >> 5;
    int lane = threadIdx.x & 31;
    if (w >= NT) return;
    const float* xr = x + (size_t)w * DIM;
    float acc[NE];
#pragma unroll
    for (int e = 0; e < NE; e++) acc[e] = 0.f;
    for (int k = lane; k < DIM; k += 32) {
        float xv = xr[k];
        const float4 wa = *(const float4*)(rw + k * NE);
        const float4 wb = *(const float4*)(rw + k * NE + 4);
        acc[0] += xv*wa.x; acc[1] += xv*wa.y; acc[2] += xv*wa.z; acc[3] += xv*wa.w;
        acc[4] += xv*wb.x; acc[5] += xv*wb.y; acc[6] += xv*wb.z; acc[7] += xv*wb.w;
    }
#pragma unroll
    for (int off = 16; off > 0; off >>= 1)
#pragma unroll
        for (int e = 0; e < NE; e++) acc[e] += __shfl_xor_sync(0xffffffffu, acc[e], off);
    if (lane == 0) {
        float v0 = -1e30f, v1 = -1e30f; int i0 = 0, i1 = 0;
#pragma unroll
        for (int e = 0; e < NE; e++) {
            float v = acc[e];
            if (v > v0) { v1 = v0; i1 = i0; v0 = v; i0 = e; }
            else if (v > v1) { v1 = v; i1 = e; }
        }
        float w0 = 1.0f / (1.0f + expf(v1 - v0));
        float w1 = 1.0f - w0;
        g_tok_e[2*w] = i0; g_tok_e[2*w+1] = i1;
        g_tok_w[2*w] = w0; g_tok_w[2*w+1] = w1;
        atomicAdd(&g_cnt[i0], 1); atomicAdd(&g_cnt[i1], 1);
    }
}

__global__ void scan_kernel() {
    if (threadIdx.x != 0 || blockIdx.x != 0) return;
    int off = 0, tile = 0;
    for (int e = 0; e < NE; e++) {
        int c = g_cnt[e];
        g_cursor[e] = off;
        int nt = (c + 127) >> 7;
        for (int i = 0; i < nt; i++) {
            g_tile_e[tile] = e; g_tile_m[tile] = off + (i << 7); tile++;
        }
        off += nt << 7;
    }
    for (; tile < MAXTILES; tile++) g_tile_e[tile] = -1;
}

__global__ void scatter_kernel() {
    int t = blockIdx.x * 256 + threadIdx.x;
    if (t >= NT) return;
#pragma unroll
    for (int k = 0; k < 2; k++) {
        int e = g_tok_e[2*t + k];
        int p = atomicAdd(&g_cursor[e], 1);
        g_perm[p] = t;
        g_wperm[p] = g_tok_w[2*t + k];
        g_pos[2*t + k] = p;
    }
}

__global__ void cvtx_kernel(const float* __restrict__ x) {
    size_t i = ((size_t)blockIdx.x * 256 + threadIdx.x) * 4;
    float4 v = *(const float4*)(x + i);
    union { __half2 h[2]; uint2 u; } pk;
    pk.h[0] = __floats2half2_rn(v.x, v.y);
    pk.h[1] = __floats2half2_rn(v.z, v.w);
    *(uint2*)(g_xh + i) = pk.u;
}

// transpose + convert: in fp32 [R,C] (row-major) -> out fp16 [C,R] (K-major for MMA)
__global__ void tcvt_kernel(const float* __restrict__ in, int w2sel, size_t outOff, int R, int C) {
    __shared__ float t[32][33];
    int z = blockIdx.z;
    in += (size_t)z * R * C;
    __half* out = (w2sel ? g_w2t : g_w1t) + outOff + (size_t)z * R * C;
    int r0 = blockIdx.y * 32, c0 = blockIdx.x * 32;
    int tx = threadIdx.x, ty = threadIdx.y;
#pragma unroll
    for (int i = 0; i < 32; i += 8)
        t[ty + i][tx] = in[(size_t)(r0 + ty + i) * C + (c0 + tx)];
    __syncthreads();
#pragma unroll
    for (int i = 0; i < 32; i += 8)
        out[(size_t)(c0 + ty + i) * R + (r0 + tx)] = __float2half(t[tx][ty + i]);
}

__global__ void combine_kernel(float* __restrict__ out) {
    int t = blockIdx.x;
    int c = threadIdx.x * 4;
    int p0 = g_pos[2*t], p1 = g_pos[2*t + 1];
    float w0 = g_wperm[p0], w1 = g_wperm[p1];
    float4 o = *(float4*)(out + (size_t)t * DIM + c);
    float4 a = *(const float4*)(g_P + (size_t)p0 * DIM + c);
    float4 b = *(const float4*)(g_P + (size_t)p1 * DIM + c);
    o.x += w0*a.x + w1*b.x; o.y += w0*a.y + w1*b.y;
    o.z += w0*a.z + w1*b.z; o.w += w0*a.w + w1*b.w;
    *(float4*)(out + (size_t)t * DIM + c) = o;
}

// ---------------- fp16 HMMA GEMM, 3-stage cp.async ----------------
// C[128,128-tile] = A[128,K] @ B^T (B stored [N,K]).
// CDST: 0 -> g_H (fp16, relu), 1 -> outp (fp32), 2 -> g_P (fp32)
template<int KD, int ND, bool GROUPED, bool GATHER, bool RELU, int CDST, bool A_H, bool W1SEL>
__global__ void __launch_bounds__(256, 2) gemm_hmma(float* __restrict__ outp) {
    constexpr int BK = 32, KT = KD / BK;
    constexpr int AST = 40;                        // halves per smem row (80B, ldmatrix conflict-free)
    constexpr int TILEB = 128 * AST * 2;           // 10240 B per tile
    constexpr int STAGEB = 2 * TILEB;              // A+B per stage = 20480 B
    extern __shared__ __half sm[];                 // 3 stages = 61440 B

    const __half* A = A_H ? g_H : g_xh;
    const __half* B = W1SEL ? g_w1t : g_w2t;
    int mbase;
    if (GROUPED) {
        int e = g_tile_e[blockIdx.y];
        if (e < 0) return;
        mbase = g_tile_m[blockIdx.y];
        B += (size_t)(1 + e) * KD * ND;
    } else {
        mbase = blockIdx.y * 128;
    }
    const int nbase = blockIdx.x * 128;
    const int tid = threadIdx.x, warp = tid >> 5, lane = tid & 31;
    const int wr = warp & 3, wc = warp >> 2;       // warp tile 32(m) x 64(n)
    const int g = lane >> 2, tg = lane & 3;

    // global->smem mapping: idx -> row idx>>2, 16B chunk idx&3 (2 chunks per thread per tile)
    const __half* aPtr[2]; const __half* bPtr[2];
    uint32_t sAoff[2], sBoff[2];
    const uint32_t smb = smem_u32(sm);
#pragma unroll
    for (int i = 0; i < 2; i++) {
        int idx = tid + i * 256, row = idx >> 2, ch = idx & 3;
        sAoff[i] = smb + (row * AST + ch * 8) * 2;
        sBoff[i] = sAoff[i] + TILEB;
        int ar = mbase + row;
        if (GATHER) ar = g_perm[ar];
        aPtr[i] = A + (size_t)ar * KD + ch * 8;
        bPtr[i] = B + (size_t)(nbase + row) * KD + ch * 8;
    }

    // ldmatrix address bases: row = (lane&7) + bit3*8, kcol = bit4*8
    const int lr = (lane & 7) + ((lane >> 3) & 1) * 8;
    const int lk = (lane >> 4) * 8;
    const uint32_t aBase = smb + ((wr * 32 + lr) * AST + lk) * 2;
    const uint32_t bBase = smb + TILEB + ((wc * 64 + lr) * AST + lk) * 2;

    float acc[2][8][4];
#pragma unroll
    for (int a = 0; a < 2; a++)
#pragma unroll
        for (int b = 0; b < 8; b++)
#pragma unroll
            for (int c = 0; c < 4; c++) acc[a][b][c] = 0.f;

#define ISSUE_STAGE(kt_, s_) do {                                             \
        uint32_t so_ = (uint32_t)(s_) * STAGEB;                               \
        _Pragma("unroll")                                                     \
        for (int i_ = 0; i_ < 2; i_++) cpa16(sAoff[i_] + so_, aPtr[i_] + (kt_) * BK); \
        _Pragma("unroll")                                                     \
        for (int i_ = 0; i_ < 2; i_++) cpa16(sBoff[i_] + so_, bPtr[i_] + (kt_) * BK); \
        asm volatile("cp.async.commit_group;" ::: "memory");                  \
    } while (0)

    ISSUE_STAGE(0, 0);
    ISSUE_STAGE(1, 1);

    int s = 0;
    for (int kt = 0; kt < KT; kt++) {
        // drain rule: while groups are still being committed each iteration,
        // wait_group 1 leaves exactly group kt complete; in the FINAL iteration
        // no new commit happened, so we must drain fully (wait_group 0).
        if (kt + 1 < KT) asm volatile("cp.async.wait_group 1;" ::: "memory");
        else             asm volatile("cp.async.wait_group 0;" ::: "memory");
        __syncthreads();
        if (kt + 2 < KT) {
            int s2 = s + 2; if (s2 >= 3) s2 -= 3;
            ISSUE_STAGE(kt + 2, s2);
        }
        const uint32_t ab = aBase + s * STAGEB;
        const uint32_t bb = bBase + s * STAGEB;
#pragma unroll
        for (int kg = 0; kg < 2; kg++) {
            uint32_t af[2][4];
            ldm4(af[0], ab + kg * 32);
            ldm4(af[1], ab + 1280 + kg * 32);      // +16 rows
#pragma unroll
            for (int nj = 0; nj < 4; nj++) {
                uint32_t bf[4];
                ldm4(bf, bb + nj * 1280 + kg * 32);
                mma16816(acc[0][2*nj],     af[0], bf[0], bf[2]);
                mma16816(acc[0][2*nj + 1], af[0], bf[1], bf[3]);
                mma16816(acc[1][2*nj],     af[1], bf[0], bf[2]);
                mma16816(acc[1][2*nj + 1], af[1], bf[1], bf[3]);
            }
        }
        s = (s + 1 == 3) ? 0 : s + 1;
    }
#undef ISSUE_STAGE

    // epilogue: d0,d1 -> (row g, cols 2tg..), d2,d3 -> (row g+8, same cols)
#pragma unroll
    for (int mi = 0; mi < 2; mi++) {
        const int r0 = mbase + wr * 32 + mi * 16 + g;
#pragma unroll
        for (int ni = 0; ni < 8; ni++) {
            const int c = nbase + wc * 64 + ni * 8 + tg * 2;
            float x0 = acc[mi][ni][0], x1 = acc[mi][ni][1];
            float x2 = acc[mi][ni][2], x3 = acc[mi][ni][3];
            if (RELU) { x0 = fmaxf(x0, 0.f); x1 = fmaxf(x1, 0.f);
                        x2 = fmaxf(x2, 0.f); x3 = fmaxf(x3, 0.f); }
            if (CDST == 0) {
                *(__half2*)(g_H + (size_t)r0 * ND + c)       = __floats2half2_rn(x0, x1);
                *(__half2*)(g_H + (size_t)(r0 + 8) * ND + c) = __floats2half2_rn(x2, x3);
            } else {
                float* base = (CDST == 1) ? outp : (float*)g_P;
                *(float2*)(base + (size_t)r0 * ND + c)       = make_float2(x0, x1);
                *(float2*)(base + (size_t)(r0 + 8) * ND + c) = make_float2(x2, x3);
            }
        }
    }
}

// ---------------- launch ----------------
extern "C" void kernel_launch(void* const* d_in, const int* in_sizes, int n_in,
                              void* d_out, int out_size) {
    const float* x   = (const float*)d_in[0];
    const float* sw1 = (const float*)d_in[1];
    const float* sw2 = (const float*)d_in[2];
    const float* rw1 = (const float*)d_in[3];
    const float* rw2 = (const float*)d_in[4];
    const float* rtw = (const float*)d_in[5];
    float* out = (float*)d_out;

    constexpr int GSMEM = 3 * 2 * 128 * 40 * 2;   // 61440 B

    auto s1 = gemm_hmma<DIM,   INTER, false, false, true,  0, false, true >;
    auto s2 = gemm_hmma<INTER, DIM,   false, false, false, 1, true,  false>;
    auto r1 = gemm_hmma<DIM,   INTER, true,  true,  true,  0, false, true >;
    auto r2 = gemm_hmma<INTER, DIM,   true,  false, false, 2, true,  false>;
    cudaFuncSetAttribute(s1, cudaFuncAttributeMaxDynamicSharedMemorySize, GSMEM);
    cudaFuncSetAttribute(s2, cudaFuncAttributeMaxDynamicSharedMemorySize, GSMEM);
    cudaFuncSetAttribute(r1, cudaFuncAttributeMaxDynamicSharedMemorySize, GSMEM);
    cudaFuncSetAttribute(r2, cudaFuncAttributeMaxDynamicSharedMemorySize, GSMEM);

    // launches 1-5: converts, so launch 6 (captured by ncu -s 5 -c 1) is the big GEMM
    dim3 tb(32, 8);
    cvtx_kernel<<<NT * DIM / 1024, 256>>>(x);
    tcvt_kernel<<<dim3(INTER/32, DIM/32, 1),  tb>>>(sw1, 0, 0, DIM, INTER);
    tcvt_kernel<<<dim3(DIM/32, INTER/32, 1),  tb>>>(sw2, 1, 0, INTER, DIM);
    tcvt_kernel<<<dim3(INTER/32, DIM/32, NE), tb>>>(rw1, 0, (size_t)INTER * DIM, DIM, INTER);
    tcvt_kernel<<<dim3(DIM/32, INTER/32, NE), tb>>>(rw2, 1, (size_t)DIM * INTER, INTER, DIM);

    s1<<<dim3(INTER/128, NT/128), 256, GSMEM>>>(out);   // launch #6

    init_kernel   <<<(MAXROWS + 255) / 256, 256>>>();
    router_kernel <<<NT / 8, 256>>>(x, rtw);
    scan_kernel   <<<1, 32>>>();
    scatter_kernel<<<NT / 256, 256>>>();

    s2<<<dim3(DIM/128,   NT/128), 256, GSMEM>>>(out);
    r1<<<dim3(INTER/128, MAXTILES), 256, GSMEM>>>(out);
    r2<<<dim3(DIM/128,   MAXTILES), 256, GSMEM>>>(out);

    combine_kernel<<<NT, 256>>>(out);
}

// round 7
// speedup vs baseline: 2.3979x; 1.0659x over previous
#include <cuda_runtime.h>
#include <cuda_fp16.h>
#include <cstdint>

#define NT    8192
#define DIM   1024
#define INTER 4096
#define NE    8
#define MAXROWS  17408      // 2*NT + NE*128 (expert segments padded to 128)
#define MAXTILES 136        // MAXROWS/128

// ---------------- scratch (device globals: no allocations allowed) ----------------
__device__ __half g_xh[(size_t)NT * DIM];
__device__ __half g_H[(size_t)MAXROWS * INTER];
__device__ __half g_w1t[(size_t)(NE + 1) * INTER * DIM];   // [1+E][INTER][DIM]  (W1^T, K-major)
__device__ __half g_w2t[(size_t)(NE + 1) * DIM * INTER];   // [1+E][DIM][INTER]  (W2^T, K-major)
__device__ float  g_P[(size_t)MAXROWS * DIM];              // routed partials (permuted rows)
__device__ int    g_perm[MAXROWS];
__device__ float  g_wperm[MAXROWS];
__device__ int    g_pos[NT * 2];
__device__ int    g_tok_e[NT * 2];
__device__ float  g_tok_w[NT * 2];
__device__ int    g_cnt[NE];
__device__ int    g_cursor[NE];
__device__ int    g_tile_e[MAXTILES];
__device__ int    g_tile_m[MAXTILES];

// ---------------- PTX helpers ----------------
__device__ __forceinline__ uint32_t smem_u32(const void* p) {
    uint32_t a;
    asm("{ .reg .u64 t; cvta.to.shared.u64 t, %1; cvt.u32.u64 %0, t; }" : "=r"(a) : "l"(p));
    return a;
}
__device__ __forceinline__ void ldm4(uint32_t* r, uint32_t addr) {
    asm volatile("ldmatrix.sync.aligned.m8n8.x4.shared.b16 {%0,%1,%2,%3}, [%4];"
                 : "=r"(r[0]), "=r"(r[1]), "=r"(r[2]), "=r"(r[3]) : "r"(addr));
}
__device__ __forceinline__ void mma16816(float* d, const uint32_t* a, uint32_t b0, uint32_t b1) {
    asm volatile(
        "mma.sync.aligned.m16n8k16.row.col.f32.f16.f16.f32 "
        "{%0,%1,%2,%3},{%4,%5,%6,%7},{%8,%9},{%0,%1,%2,%3};"
        : "+f"(d[0]), "+f"(d[1]), "+f"(d[2]), "+f"(d[3])
        : "r"(a[0]), "r"(a[1]), "r"(a[2]), "r"(a[3]), "r"(b0), "r"(b1));
}
__device__ __forceinline__ void cpa16(uint32_t dst, const void* src) {
    asm volatile("cp.async.cg.shared.global [%0], [%1], 16;" :: "r"(dst), "l"(src));
}

// ---------------- small kernels ----------------
__global__ void init_kernel() {
    int i = blockIdx.x * 256 + threadIdx.x;
    if (i < NE) g_cnt[i] = 0;
    if (i < MAXROWS) { g_perm[i] = 0; g_wperm[i] = 0.0f; }
}

__global__ void router_kernel(const float* __restrict__ x, const float* __restrict__ rw) {
    int w = (blockIdx.x * blockDim.x + threadIdx.x) >> 5;
    int lane = threadIdx.x & 31;
    if (w >= NT) return;
    const float* xr = x + (size_t)w * DIM;
    float acc[NE];
#pragma unroll
    for (int e = 0; e < NE; e++) acc[e] = 0.f;
    for (int k = lane; k < DIM; k += 32) {
        float xv = xr[k];
        const float4 wa = *(const float4*)(rw + k * NE);
        const float4 wb = *(const float4*)(rw + k * NE + 4);
        acc[0] += xv*wa.x; acc[1] += xv*wa.y; acc[2] += xv*wa.z; acc[3] += xv*wa.w;
        acc[4] += xv*wb.x; acc[5] += xv*wb.y; acc[6] += xv*wb.z; acc[7] += xv*wb.w;
    }
#pragma unroll
    for (int off = 16; off > 0; off >>= 1)
#pragma unroll
        for (int e = 0; e < NE; e++) acc[e] += __shfl_xor_sync(0xffffffffu, acc[e], off);
    if (lane == 0) {
        float v0 = -1e30f, v1 = -1e30f; int i0 = 0, i1 = 0;
#pragma unroll
        for (int e = 0; e < NE; e++) {
            float v = acc[e];
            if (v > v0) { v1 = v0; i1 = i0; v0 = v; i0 = e; }
            else if (v > v1) { v1 = v; i1 = e; }
        }
        float w0 = 1.0f / (1.0f + expf(v1 - v0));
        float w1 = 1.0f - w0;
        g_tok_e[2*w] = i0; g_tok_e[2*w+1] = i1;
        g_tok_w[2*w] = w0; g_tok_w[2*w+1] = w1;
        atomicAdd(&g_cnt[i0], 1); atomicAdd(&g_cnt[i1], 1);
    }
}

__global__ void scan_kernel() {
    if (threadIdx.x != 0 || blockIdx.x != 0) return;
    int off = 0, tile = 0;
    for (int e = 0; e < NE; e++) {
        int c = g_cnt[e];
        g_cursor[e] = off;
        int nt = (c + 127) >> 7;
        for (int i = 0; i < nt; i++) {
            g_tile_e[tile] = e; g_tile_m[tile] = off + (i << 7); tile++;
        }
        off += nt << 7;
    }
    for (; tile < MAXTILES; tile++) g_tile_e[tile] = -1;
}

__global__ void scatter_kernel() {
    int t = blockIdx.x * 256 + threadIdx.x;
    if (t >= NT) return;
#pragma unroll
    for (int k = 0; k < 2; k++) {
        int e = g_tok_e[2*t + k];
        int p = atomicAdd(&g_cursor[e], 1);
        g_perm[p] = t;
        g_wperm[p] = g_tok_w[2*t + k];
        g_pos[2*t + k] = p;
    }
}

__global__ void cvtx_kernel(const float* __restrict__ x) {
    size_t i = ((size_t)blockIdx.x * 256 + threadIdx.x) * 4;
    float4 v = *(const float4*)(x + i);
    union { __half2 h[2]; uint2 u; } pk;
    pk.h[0] = __floats2half2_rn(v.x, v.y);
    pk.h[1] = __floats2half2_rn(v.z, v.w);
    *(uint2*)(g_xh + i) = pk.u;
}

// transpose + convert: in fp32 [R,C] (row-major) -> out fp16 [C,R] (K-major for MMA)
// 64x64 tiles; half2 writes give full 128B store sectors.
__global__ void tcvt_kernel(const float* __restrict__ in, int w2sel, size_t outOff, int R, int C) {
    __shared__ float t[64][65];
    int z = blockIdx.z;
    in += (size_t)z * R * C;
    __half* out = (w2sel ? g_w2t : g_w1t) + outOff + (size_t)z * R * C;
    int r0 = blockIdx.y * 64, c0 = blockIdx.x * 64;
    int tx = threadIdx.x, ty = threadIdx.y;
#pragma unroll
    for (int i = 0; i < 8; i++) {
        int row = ty + i * 8;
        const float* p = in + (size_t)(r0 + row) * C + c0 + tx;
        t[row][tx]      = p[0];
        t[row][tx + 32] = p[32];
    }
    __syncthreads();
#pragma unroll
    for (int i = 0; i < 8; i++) {
        int c = ty + i * 8;
        __half2 v = __floats2half2_rn(t[2*tx][c], t[2*tx + 1][c]);
        *(__half2*)(out + (size_t)(c0 + c) * R + r0 + 2*tx) = v;
    }
}

__global__ void combine_kernel(float* __restrict__ out) {
    int t = blockIdx.x;
    int c = threadIdx.x * 4;
    int p0 = g_pos[2*t], p1 = g_pos[2*t + 1];
    float w0 = g_wperm[p0], w1 = g_wperm[p1];
    float4 o = *(float4*)(out + (size_t)t * DIM + c);
    float4 a = *(const float4*)(g_P + (size_t)p0 * DIM + c);
    float4 b = *(const float4*)(g_P + (size_t)p1 * DIM + c);
    o.x += w0*a.x + w1*b.x; o.y += w0*a.y + w1*b.y;
    o.z += w0*a.z + w1*b.z; o.w += w0*a.w + w1*b.w;
    *(float4*)(out + (size_t)t * DIM + c) = o;
}

// ---------------- fp16 HMMA GEMM, 3-stage cp.async, BK=64 ----------------
// C[128,128-tile] = A[128,K] @ B^T (B stored [N,K]).
// CDST: 0 -> g_H (fp16, relu), 1 -> outp (fp32), 2 -> g_P (fp32)
template<int KD, int ND, bool GROUPED, bool GATHER, bool RELU, int CDST, bool A_H, bool W1SEL>
__global__ void __launch_bounds__(256, 2) gemm_hmma(float* __restrict__ outp) {
    constexpr int BK = 64, KT = KD / BK;
    constexpr int AST = 72;                        // halves per smem row (144B, ldmatrix conflict-free)
    constexpr int TILEB = 128 * AST * 2;           // 18432 B per tile
    constexpr int STAGEB = 2 * TILEB;              // A+B per stage = 36864 B
    extern __shared__ __half sm[];                 // 3 stages = 110592 B

    const __half* A = A_H ? g_H : g_xh;
    const __half* B = W1SEL ? g_w1t : g_w2t;
    int mbase;
    if (GROUPED) {
        int e = g_tile_e[blockIdx.y];
        if (e < 0) return;
        mbase = g_tile_m[blockIdx.y];
        B += (size_t)(1 + e) * KD * ND;
    } else {
        mbase = blockIdx.y * 128;
    }
    const int nbase = blockIdx.x * 128;
    const int tid = threadIdx.x, warp = tid >> 5, lane = tid & 31;
    const int wr = warp & 3, wc = warp >> 2;       // warp tile 32(m) x 64(n)
    const int g = lane >> 2, tg = lane & 3;

    // global->smem mapping: idx -> row idx>>3, 16B chunk idx&7 (4 chunks/thread/tile)
    const __half* aPtr[4]; const __half* bPtr[4];
    uint32_t sAoff[4], sBoff[4];
    const uint32_t smb = smem_u32(sm);
#pragma unroll
    for (int i = 0; i < 4; i++) {
        int idx = tid + i * 256, row = idx >> 3, ch = idx & 7;
        sAoff[i] = smb + (row * AST + ch * 8) * 2;
        sBoff[i] = sAoff[i] + TILEB;
        int ar = mbase + row;
        if (GATHER) ar = g_perm[ar];
        aPtr[i] = A + (size_t)ar * KD + ch * 8;
        bPtr[i] = B + (size_t)(nbase + row) * KD + ch * 8;
    }

    // ldmatrix address bases: row = (lane&7) + bit3*8, kcol = bit4*8
    const int lr = (lane & 7) + ((lane >> 3) & 1) * 8;
    const int lk = (lane >> 4) * 8;
    const uint32_t aBase = smb + ((wr * 32 + lr) * AST + lk) * 2;
    const uint32_t bBase = smb + TILEB + ((wc * 64 + lr) * AST + lk) * 2;
    constexpr int ROW16 = 16 * AST * 2;            // 2304 B: 16-row jump

    float acc[2][8][4];
#pragma unroll
    for (int a = 0; a < 2; a++)
#pragma unroll
        for (int b = 0; b < 8; b++)
#pragma unroll
            for (int c = 0; c < 4; c++) acc[a][b][c] = 0.f;

#define ISSUE_STAGE(kt_, s_) do {                                             \
        uint32_t so_ = (uint32_t)(s_) * STAGEB;                               \
        _Pragma("unroll")                                                     \
        for (int i_ = 0; i_ < 4; i_++) cpa16(sAoff[i_] + so_, aPtr[i_] + (kt_) * BK); \
        _Pragma("unroll")                                                     \
        for (int i_ = 0; i_ < 4; i_++) cpa16(sBoff[i_] + so_, bPtr[i_] + (kt_) * BK); \
        asm volatile("cp.async.commit_group;" ::: "memory");                  \
    } while (0)

    ISSUE_STAGE(0, 0);
    ISSUE_STAGE(1, 1);

    int s = 0;
    for (int kt = 0; kt < KT; kt++) {
        // drain rule: final iteration has no new commit, so it must drain fully.
        if (kt + 1 < KT) asm volatile("cp.async.wait_group 1;" ::: "memory");
        else             asm volatile("cp.async.wait_group 0;" ::: "memory");
        __syncthreads();
        if (kt + 2 < KT) {
            int s2 = s + 2; if (s2 >= 3) s2 -= 3;
            ISSUE_STAGE(kt + 2, s2);
        }
        const uint32_t ab = aBase + s * STAGEB;
        const uint32_t bb = bBase + s * STAGEB;
#pragma unroll
        for (int kg = 0; kg < 4; kg++) {
            uint32_t af[2][4];
            ldm4(af[0], ab + kg * 32);
            ldm4(af[1], ab + ROW16 + kg * 32);
#pragma unroll
            for (int nj = 0; nj < 4; nj++) {
                uint32_t bf[4];
                ldm4(bf, bb + nj * ROW16 + kg * 32);
                mma16816(acc[0][2*nj],     af[0], bf[0], bf[2]);
                mma16816(acc[0][2*nj + 1], af[0], bf[1], bf[3]);
                mma16816(acc[1][2*nj],     af[1], bf[0], bf[2]);
                mma16816(acc[1][2*nj + 1], af[1], bf[1], bf[3]);
            }
        }
        s = (s + 1 == 3) ? 0 : s + 1;
    }
#undef ISSUE_STAGE

    // epilogue: d0,d1 -> (row g, cols 2tg..), d2,d3 -> (row g+8, same cols)
#pragma unroll
    for (int mi = 0; mi < 2; mi++) {
        const int r0 = mbase + wr * 32 + mi * 16 + g;
#pragma unroll
        for (int ni = 0; ni < 8; ni++) {
            const int c = nbase + wc * 64 + ni * 8 + tg * 2;
            float x0 = acc[mi][ni][0], x1 = acc[mi][ni][1];
            float x2 = acc[mi][ni][2], x3 = acc[mi][ni][3];
            if (RELU) { x0 = fmaxf(x0, 0.f); x1 = fmaxf(x1, 0.f);
                        x2 = fmaxf(x2, 0.f); x3 = fmaxf(x3, 0.f); }
            if (CDST == 0) {
                *(__half2*)(g_H + (size_t)r0 * ND + c)       = __floats2half2_rn(x0, x1);
                *(__half2*)(g_H + (size_t)(r0 + 8) * ND + c) = __floats2half2_rn(x2, x3);
            } else {
                float* base = (CDST == 1) ? outp : (float*)g_P;
                *(float2*)(base + (size_t)r0 * ND + c)       = make_float2(x0, x1);
                *(float2*)(base + (size_t)(r0 + 8) * ND + c) = make_float2(x2, x3);
            }
        }
    }
}

// ---------------- launch ----------------
extern "C" void kernel_launch(void* const* d_in, const int* in_sizes, int n_in,
                              void* d_out, int out_size) {
    const float* x   = (const float*)d_in[0];
    const float* sw1 = (const float*)d_in[1];
    const float* sw2 = (const float*)d_in[2];
    const float* rw1 = (const float*)d_in[3];
    const float* rw2 = (const float*)d_in[4];
    const float* rtw = (const float*)d_in[5];
    float* out = (float*)d_out;

    constexpr int GSMEM = 3 * 2 * 128 * 72 * 2;   // 110592 B

    auto s1 = gemm_hmma<DIM,   INTER, false, false, true,  0, false, true >;
    auto s2 = gemm_hmma<INTER, DIM,   false, false, false, 1, true,  false>;
    auto r1 = gemm_hmma<DIM,   INTER, true,  true,  true,  0, false, true >;
    auto r2 = gemm_hmma<INTER, DIM,   true,  false, false, 2, true,  false>;
    cudaFuncSetAttribute(s1, cudaFuncAttributeMaxDynamicSharedMemorySize, GSMEM);
    cudaFuncSetAttribute(s2, cudaFuncAttributeMaxDynamicSharedMemorySize, GSMEM);
    cudaFuncSetAttribute(r1, cudaFuncAttributeMaxDynamicSharedMemorySize, GSMEM);
    cudaFuncSetAttribute(r2, cudaFuncAttributeMaxDynamicSharedMemorySize, GSMEM);

    // the profiler captures the 4th launch -> put the big shared GEMM there
    dim3 tb(32, 8);
    cvtx_kernel<<<NT * DIM / 1024, 256>>>(x);                                   // 1
    tcvt_kernel<<<dim3(INTER/64, DIM/64, 1),  tb>>>(sw1, 0, 0, DIM, INTER);     // 2
    tcvt_kernel<<<dim3(DIM/64, INTER/64, 1),  tb>>>(sw2, 1, 0, INTER, DIM);     // 3
    s1<<<dim3(INTER/128, NT/128), 256, GSMEM>>>(out);                           // 4  <- profiled
    tcvt_kernel<<<dim3(INTER/64, DIM/64, NE), tb>>>(rw1, 0, (size_t)INTER * DIM, DIM, INTER);
    tcvt_kernel<<<dim3(DIM/64, INTER/64, NE), tb>>>(rw2, 1, (size_t)DIM * INTER, INTER, DIM);

    init_kernel   <<<(MAXROWS + 255) / 256, 256>>>();
    router_kernel <<<NT / 8, 256>>>(x, rtw);
    scan_kernel   <<<1, 32>>>();
    scatter_kernel<<<NT / 256, 256>>>();

    s2<<<dim3(DIM/128,   NT/128), 256, GSMEM>>>(out);
    r1<<<dim3(INTER/128, MAXTILES), 256, GSMEM>>>(out);
    r2<<<dim3(DIM/128,   MAXTILES), 256, GSMEM>>>(out);

    combine_kernel<<<NT, 256>>>(out);
}